// round 15
// baseline (speedup 1.0000x reference)
#include <cuda_runtime.h>
#include <cuda_fp16.h>
#include <cstdint>

// ============================================================================
// ContraNorm: out = 1.1*x - 0.1 * softmax(xn @ xn^T) @ x,   N=16384, D=256
// Flash formulation, mma.sync m16n8k16, cp.async double buffering with
// mbarrier-tracked readiness. 4x4 warp grid; PV B via ldmatrix.trans of the
// K tile (fp16 norm folded into P). R15 (base R13): PV remaining-steps loop
// gets A-fragment double-buffering (the dependency head); early mb_free.
// ============================================================================

#define N_ROWS 16384
#define DIM    256
#define BM     128
#define BN     128
#define NTILES (N_ROWS / BN)

__device__ __align__(16) __half g_xn[(size_t)N_ROWS * DIM];  // normalized rows (fp16)
__device__ __align__(16) __half g_xq[(size_t)N_ROWS * DIM];  // normalized * log2e
__device__ __align__(16) __half g_norm[N_ROWS];              // row L2 norms (fp16)

// ---------------------------------------------------------------------------
__device__ __forceinline__ uint32_t smem_to_u32(const void* p) {
    uint32_t a;
    asm("{ .reg .u64 t; cvta.to.shared.u64 t, %1; cvt.u32.u64 %0, t; }" : "=r"(a) : "l"(p));
    return a;
}

__device__ __forceinline__ void ldsm_x4(uint32_t (&r)[4], uint32_t addr) {
    asm volatile("ldmatrix.sync.aligned.m8n8.x4.shared.b16 {%0,%1,%2,%3}, [%4];"
        : "=r"(r[0]), "=r"(r[1]), "=r"(r[2]), "=r"(r[3]) : "r"(addr));
}
__device__ __forceinline__ void ldsm_x4_t(uint32_t (&r)[4], uint32_t addr) {
    asm volatile("ldmatrix.sync.aligned.m8n8.x4.trans.shared.b16 {%0,%1,%2,%3}, [%4];"
        : "=r"(r[0]), "=r"(r[1]), "=r"(r[2]), "=r"(r[3]) : "r"(addr));
}

// fp16-accum fp16 mma (QK and PV)
__device__ __forceinline__ void mma_f16h(uint32_t (&c)[2], const uint32_t (&a)[4],
                                         uint32_t b0, uint32_t b1) {
    asm volatile(
        "mma.sync.aligned.m16n8k16.row.col.f16.f16.f16.f16 "
        "{%0,%1}, {%2,%3,%4,%5}, {%6,%7}, {%0,%1};"
        : "+r"(c[0]), "+r"(c[1])
        : "r"(a[0]), "r"(a[1]), "r"(a[2]), "r"(a[3]), "r"(b0), "r"(b1));
}

// half2 2^x
__device__ __forceinline__ uint32_t ex2_h2(uint32_t x) {
    uint32_t y;
    asm("ex2.approx.f16x2 %0, %1;" : "=r"(y) : "r"(x));
    return y;
}

#define STS32(smem_addr, v) \
    asm volatile("st.shared.b32 [%0], %1;" :: "r"(smem_addr), "r"(v) : "memory")

#define BAR_SYNC(id, cnt) \
    asm volatile("bar.sync %0, %1;" :: "r"(id), "r"(cnt) : "memory")

#define CP_ASYNC16(dst, src) \
    asm volatile("cp.async.cg.shared.global [%0], [%1], 16;" :: "r"(dst), "l"(src) : "memory")

#define CP_MBAR_ARRIVE_NOINC(mbar) \
    asm volatile("cp.async.mbarrier.arrive.noinc.shared.b64 [%0];" :: "r"((uint32_t)(mbar)) : "memory")

#define MBARRIER_INIT(mbar, cnt) \
    asm volatile("mbarrier.init.shared.b64 [%0], %1;" :: "r"((uint32_t)(mbar)), "r"((uint32_t)(cnt)) : "memory")
#define MBARRIER_ARRIVE(mbar) \
    asm volatile("mbarrier.arrive.shared.b64 _, [%0];" :: "r"((uint32_t)(mbar)) : "memory")

#define MBARRIER_WAIT_PARITY(mbar_smem_addr, phase_parity) do { \
    uint32_t _mbar = (uint32_t)(mbar_smem_addr); \
    uint32_t _parity = (uint32_t)(phase_parity); \
    uint32_t _done; \
    asm volatile( \
        "{\n\t.reg .pred p;\n\t" \
        "mbarrier.try_wait.parity.acquire.cta.shared::cta.b64 p, [%1], %2;\n\t" \
        "selp.b32 %0, 1, 0, p;\n\t}" \
        : "=r"(_done) : "r"(_mbar), "r"(_parity) : "memory"); \
    if (!_done) { \
        asm volatile( \
            "{\n\t.reg .pred P1;\n\t" \
            "WAIT_LOOP_%=:\n\t" \
            "mbarrier.try_wait.parity.acquire.cta.shared::cta.b64 P1, [%0], %1, 0x989680;\n\t" \
            "@P1 bra.uni WAIT_DONE_%=;\n\t" \
            "bra.uni WAIT_LOOP_%=;\n\t" \
            "WAIT_DONE_%=:\n\t}" \
            :: "r"(_mbar), "r"(_parity) : "memory"); \
    } \
} while(0)

// SMEM layout (bytes)
#define SQ  0           // Q tile   [128][256] fp16, row stride 512 B (swizzled)
#define SK0 65536       // K tile buf0
#define SK1 131072      // K tile buf1
#define SP  196608      // P tile [128][128] fp16, row stride 256 B (swizzled)
#define SN  229376      // fp16 norms: 2 x 256 B
#define SMB 230400      // mbarriers: full0, full1, free0, free1 (8 B each)
#define SMEM_TOTAL 230528

// ---------------------------------------------------------------------------
// Prologue: per-row L2 normalize fp32 -> fp16 (xn and xn*log2e), fp16 norms
// ---------------------------------------------------------------------------
__global__ void normalize_kernel(const float* __restrict__ x) {
    int row  = blockIdx.x * 8 + (threadIdx.x >> 5);
    int lane = threadIdx.x & 31;
    const float4* xr = reinterpret_cast<const float4*>(x + (size_t)row * DIM);
    float4 a = xr[lane * 2];
    float4 b = xr[lane * 2 + 1];
    float ss = a.x*a.x + a.y*a.y + a.z*a.z + a.w*a.w
             + b.x*b.x + b.y*b.y + b.z*b.z + b.w*b.w;
    #pragma unroll
    for (int o = 16; o > 0; o >>= 1) ss += __shfl_xor_sync(0xFFFFFFFFu, ss, o);
    float nrm = sqrtf(ss);
    float inv = 1.0f / fmaxf(nrm, 1e-12f);
    float invq = inv * 1.4426950408889634f;   // log2(e)

    __half2 p0 = __floats2half2_rn(a.x * inv, a.y * inv);
    __half2 p1 = __floats2half2_rn(a.z * inv, a.w * inv);
    __half2 p2 = __floats2half2_rn(b.x * inv, b.y * inv);
    __half2 p3 = __floats2half2_rn(b.z * inv, b.w * inv);
    uint4 v;
    v.x = *reinterpret_cast<uint32_t*>(&p0);
    v.y = *reinterpret_cast<uint32_t*>(&p1);
    v.z = *reinterpret_cast<uint32_t*>(&p2);
    v.w = *reinterpret_cast<uint32_t*>(&p3);
    *reinterpret_cast<uint4*>(&g_xn[(size_t)row * DIM + lane * 8]) = v;

    __half2 q0 = __floats2half2_rn(a.x * invq, a.y * invq);
    __half2 q1 = __floats2half2_rn(a.z * invq, a.w * invq);
    __half2 q2 = __floats2half2_rn(b.x * invq, b.y * invq);
    __half2 q3 = __floats2half2_rn(b.z * invq, b.w * invq);
    uint4 w;
    w.x = *reinterpret_cast<uint32_t*>(&q0);
    w.y = *reinterpret_cast<uint32_t*>(&q1);
    w.z = *reinterpret_cast<uint32_t*>(&q2);
    w.w = *reinterpret_cast<uint32_t*>(&q3);
    *reinterpret_cast<uint4*>(&g_xq[(size_t)row * DIM + lane * 8]) = w;

    if (lane == 0) g_norm[row] = __float2half(nrm);
}

// ---------------------------------------------------------------------------
// async prefetch of one K tile (+ its 128 fp16 norms)
// ---------------------------------------------------------------------------
__device__ __forceinline__ void prefetch_tile(uint32_t sb, int tid, int jt) {
    uint32_t kb = sb + SK0 + ((uint32_t)(jt & 1) << 16);
    const __half* src = g_xn + (size_t)jt * BN * DIM;
    #pragma unroll
    for (int it = 0; it < 8; it++) {
        int idx = tid + it * 512;
        int row = idx >> 5;
        int c16 = idx & 31;
        uint32_t dst = kb + (uint32_t)row * 512 + (((uint32_t)c16 * 16) ^ ((row & 7) << 4));
        CP_ASYNC16(dst, src + row * DIM + c16 * 8);
    }
    if (tid < 16) {
        uint32_t dst = sb + SN + ((uint32_t)(jt & 1) << 8) + (uint32_t)tid * 16;
        CP_ASYNC16(dst, g_norm + jt * BN + tid * 8);
    }
}

// ---------------------------------------------------------------------------
// Main flash kernel: 1 CTA per 128-row block, 512 threads (16 warps, 4x4)
// ---------------------------------------------------------------------------
__global__ void __launch_bounds__(512, 1)
contranorm_main(const float* __restrict__ x, float* __restrict__ out) {
    extern __shared__ __align__(1024) char smem[];
    const uint32_t sb = smem_to_u32(smem);
    const int tid  = threadIdx.x;
    const int lane = tid & 31;
    const int wid  = tid >> 5;
    const int mi   = wid >> 2;            // 0..3 row-warp group (contiguous tids)
    const int ni   = wid & 3;             // 0..3 col-warp
    const int m0   = mi * 32;             // S/O row base
    const int n0   = ni * 32;             // S col base (keys)
    const int d0   = ni * 64;             // O col base (dims)
    const int r0   = blockIdx.x * BM;

    const uint32_t mb_full = sb + SMB;        // +0: buf0, +8: buf1
    const uint32_t mb_free = sb + SMB + 16;   // +0: buf0, +8: buf1

    const int sub = lane >> 3;
    const int li  = lane & 7;
    const uint32_t XR  = (uint32_t)li << 4;
    const uint32_t csA = (uint32_t)((sub >> 1) << 4);
    const uint32_t csB = (uint32_t)((sub & 1) << 4);
    const int rowA = li + ((sub & 1) << 3);
    const int rowB = li + ((sub >> 1) << 3);
    const uint32_t d02 = (uint32_t)d0 * 2;

    // thread-constant bases
    const uint32_t a_qk = sb + SQ + (uint32_t)(m0 + rowA) * 512;
    const uint32_t a_pv = sb + SP + (uint32_t)(m0 + rowA) * 256;

    // P store / output addressing
    const int g4 = lane >> 2;             // 0..7
    const int q4 = lane & 3;              // 0..3
    const uint32_t XRp  = (uint32_t)g4 << 4;
    const uint32_t p_st0 = sb + SP + (uint32_t)(m0 + g4) * 256;

    // ---- init mbarriers ----
    if (tid == 0) {
        MBARRIER_INIT(mb_full,     512);
        MBARRIER_INIT(mb_full + 8, 512);
        MBARRIER_INIT(mb_free,     16);
        MBARRIER_INIT(mb_free + 8, 16);
    }
    __syncthreads();

    // ---- async-load Q tile (from g_xq) + tile 0 (+norms); signal full[0] ----
    {
        const __half* src = g_xq + (size_t)r0 * DIM;
        #pragma unroll
        for (int it = 0; it < 8; it++) {
            int idx = tid + it * 512;
            int row = idx >> 5;
            int c16 = idx & 31;
            uint32_t dst = sb + SQ + (uint32_t)row * 512 + (((uint32_t)c16 * 16) ^ ((row & 7) << 4));
            CP_ASYNC16(dst, src + row * DIM + c16 * 8);
        }
    }
    prefetch_tile(sb, tid, 0);
    CP_MBAR_ARRIVE_NOINC(mb_full);

    uint32_t oacc[16][2];                  // fp16x2 O accumulators
    #pragma unroll
    for (int t = 0; t < 16; t++) { oacc[t][0] = 0u; oacc[t][1] = 0u; }
    float dsum[2][2] = {{0.0f, 0.0f}, {0.0f, 0.0f}};   // [ma][lo/hi]

    for (int j = 0; j < NTILES; j++) {
        const int b = j & 1;
        const uint32_t kb = sb + SK0 + ((uint32_t)b << 16);

        // tile j data ready (cp.async completion tracked by mbarrier)
        MBARRIER_WAIT_PARITY(mb_full + b * 8, (j >> 1) & 1);

        // ---- QK^T: S[32 x 32] per warp, K=256, fp16 accumulate,
        //      operand double-buffered (ldsm of kk+1 before MMAs of kk) ----
        uint32_t sacc[8][2];
        #pragma unroll
        for (int t = 0; t < 8; t++) { sacc[t][0] = 0u; sacc[t][1] = 0u; }

        const uint32_t b_qk = kb + (uint32_t)(n0 + rowB) * 512;
        {
            uint32_t fa[2][2][4];          // [buf][a0/a1][4]
            uint32_t fb[2][2][4];          // [buf][nb2][4]
            {
                uint32_t colA = csA ^ XR;
                uint32_t colB = csB ^ XR;
                ldsm_x4(fa[0][0], a_qk + colA);
                ldsm_x4(fa[0][1], a_qk + 8192 + colA);
                ldsm_x4(fb[0][0], b_qk + colB);
                ldsm_x4(fb[0][1], b_qk + 8192 + colB);
            }
            #pragma unroll
            for (int kk = 0; kk < 16; kk++) {
                const int cur = kk & 1, nxt = cur ^ 1;
                if (kk < 15) {
                    uint32_t colA = (((uint32_t)(kk + 1) << 5) | csA) ^ XR;
                    uint32_t colB = (((uint32_t)(kk + 1) << 5) | csB) ^ XR;
                    ldsm_x4(fa[nxt][0], a_qk + colA);
                    ldsm_x4(fa[nxt][1], a_qk + 8192 + colA);
                    ldsm_x4(fb[nxt][0], b_qk + colB);
                    ldsm_x4(fb[nxt][1], b_qk + 8192 + colB);
                }
                #pragma unroll
                for (int nb2 = 0; nb2 < 2; nb2++) {
                    mma_f16h(sacc[nb2 * 2],     fa[cur][0], fb[cur][nb2][0], fb[cur][nb2][1]);
                    mma_f16h(sacc[nb2 * 2 + 1], fa[cur][0], fb[cur][nb2][2], fb[cur][nb2][3]);
                    mma_f16h(sacc[4 + nb2 * 2],     fa[cur][1], fb[cur][nb2][0], fb[cur][nb2][1]);
                    mma_f16h(sacc[4 + nb2 * 2 + 1], fa[cur][1], fb[cur][nb2][2], fb[cur][nb2][3]);
                }
            }
        }

        // ---- prefetch tile j+1 (WAR: wait until all warps done reading that buf) ----
        if (j + 1 < NTILES) {
            if (j > 0)
                MBARRIER_WAIT_PARITY(mb_free + ((j + 1) & 1) * 8, ((j - 1) >> 1) & 1);
            prefetch_tile(sb, tid, j + 1);
            CP_MBAR_ARRIVE_NOINC(mb_full + ((j + 1) & 1) * 8);
        }

        // ---- epilogue (all half2): e = 2^(S'); denom += e; P = e*norm_n ----
        const __half2* nrmh = reinterpret_cast<const __half2*>(smem + SN + (b << 8));
        uint32_t pa[2][4][2];              // [ma][nb][lo/hi] half2 P fragments
        #pragma unroll
        for (int ma = 0; ma < 2; ma++) {
            __half2 hs0 = __float2half2_rn(0.0f);
            __half2 hs1 = __float2half2_rn(0.0f);
            #pragma unroll
            for (int nb = 0; nb < 4; nb++) {
                int c = n0 + nb * 8 + q4 * 2;
                __half2 nn = nrmh[c >> 1];
                uint32_t e01u = ex2_h2(sacc[ma * 4 + nb][0]);
                uint32_t e23u = ex2_h2(sacc[ma * 4 + nb][1]);
                __half2 e01 = *reinterpret_cast<__half2*>(&e01u);
                __half2 e23 = *reinterpret_cast<__half2*>(&e23u);
                hs0 = __hadd2(hs0, e01);
                hs1 = __hadd2(hs1, e23);
                __half2 p01 = __hmul2(e01, nn);
                __half2 p23 = __hmul2(e23, nn);
                uint32_t ulo = *reinterpret_cast<uint32_t*>(&p01);
                uint32_t uhi = *reinterpret_cast<uint32_t*>(&p23);
                pa[ma][nb][0] = ulo;
                pa[ma][nb][1] = uhi;
                uint32_t addr = p_st0 + (uint32_t)ma * 4096 + (((uint32_t)c * 2) ^ XRp);
                STS32(addr, ulo);
                STS32(addr + 2048, uhi);
            }
            float2 f0 = __half22float2(hs0);
            float2 f1 = __half22float2(hs1);
            dsum[ma][0] += f0.x + f0.y;
            dsum[ma][1] += f1.x + f1.y;
        }

        // ---- PV own-key steps (A from pa registers, no P-smem dependency):
        //      run BEFORE the group barrier to overlap siblings' epilogues ----
        const uint32_t b_pv = kb + (uint32_t)rowA * 512;
        #pragma unroll
        for (int t2 = 0; t2 < 2; t2++) {
            int kk = 2 * ni + t2;
            uint32_t a0[4], a1[4];
            a0[0] = pa[0][t2 * 2][0];     a0[1] = pa[0][t2 * 2][1];
            a0[2] = pa[0][t2 * 2 + 1][0]; a0[3] = pa[0][t2 * 2 + 1][1];
            a1[0] = pa[1][t2 * 2][0];     a1[1] = pa[1][t2 * 2][1];
            a1[2] = pa[1][t2 * 2 + 1][0]; a1[3] = pa[1][t2 * 2 + 1][1];
            uint32_t rbase = b_pv + (uint32_t)kk * 8192;
            #pragma unroll
            for (int q = 0; q < 4; q++) {
                uint32_t b2[4];
                ldsm_x4_t(b2, rbase + ((d02 + ((uint32_t)q << 5) + csA) ^ XR));
                mma_f16h(oacc[q * 2],     a0, b2[0], b2[1]);
                mma_f16h(oacc[q * 2 + 1], a0, b2[2], b2[3]);
                mma_f16h(oacc[8 + q * 2],     a1, b2[0], b2[1]);
                mma_f16h(oacc[8 + q * 2 + 1], a1, b2[2], b2[3]);
            }
        }

        // own row-group's P band complete (remaining PV reads rows m0..m0+31)
        BAR_SYNC(1 + mi, 128);

        // ---- PV remaining steps: A via ldsm of P tile, A DOUBLE-BUFFERED
        //      (kk list = {0..7} minus {2ni, 2ni+1}: kk = i + (i>=2ni ? 2:0)) ----
        {
            const int twoNi = 2 * ni;
            uint32_t fa[2][2][4];
            {
                int kk0 = (0 >= twoNi) ? 2 : 0;
                uint32_t colA = (((uint32_t)kk0 << 5) | csA) ^ XR;
                ldsm_x4(fa[0][0], a_pv + colA);
                ldsm_x4(fa[0][1], a_pv + 4096 + colA);
            }
            #pragma unroll
            for (int i = 0; i < 6; i++) {
                const int cur = i & 1, nxt = cur ^ 1;
                int kk = i + ((i >= twoNi) ? 2 : 0);
                if (i < 5) {
                    int kk1 = (i + 1) + (((i + 1) >= twoNi) ? 2 : 0);
                    uint32_t colA = (((uint32_t)kk1 << 5) | csA) ^ XR;
                    ldsm_x4(fa[nxt][0], a_pv + colA);
                    ldsm_x4(fa[nxt][1], a_pv + 4096 + colA);
                }
                uint32_t rbase = b_pv + (uint32_t)kk * 8192;
                #pragma unroll
                for (int q = 0; q < 4; q++) {
                    uint32_t b2[4];
                    ldsm_x4_t(b2, rbase + ((d02 + ((uint32_t)q << 5) + csA) ^ XR));
                    mma_f16h(oacc[q * 2],     fa[cur][0], b2[0], b2[1]);
                    mma_f16h(oacc[q * 2 + 1], fa[cur][0], b2[2], b2[3]);
                    mma_f16h(oacc[8 + q * 2],     fa[cur][1], b2[0], b2[1]);
                    mma_f16h(oacc[8 + q * 2 + 1], fa[cur][1], b2[2], b2[3]);
                }
            }
        }
        // this warp done reading K buf b — release before the barrier
        if (lane == 0) MBARRIER_ARRIVE(mb_free + b * 8);
        // group done with P(j) (next tile's exp may overwrite the band)
        BAR_SYNC(1 + mi, 128);
    }

    // all PV reads of the P region must be done before reusing it as scratch
    __syncthreads();

    // ---- cross-warp denominator reduction (each warp summed 32 cols) ----
    float* sd = reinterpret_cast<float*>(smem + SP);   // reuse P region: [128][4]
    #pragma unroll
    for (int ma = 0; ma < 2; ma++) {
        #pragma unroll
        for (int lh = 0; lh < 2; lh++) {
            float d = dsum[ma][lh];
            d += __shfl_xor_sync(0xFFFFFFFFu, d, 1);
            d += __shfl_xor_sync(0xFFFFFFFFu, d, 2);
            if (q4 == 0) sd[(m0 + ma * 16 + lh * 8 + g4) * 4 + ni] = d;
        }
    }
    __syncthreads();

    // ---- final blend: out = 1.1*x - (0.1/denom) * O ----
    #pragma unroll
    for (int ma = 0; ma < 2; ma++) {
        int rl = m0 + ma * 16 + g4;
        int rh = rl + 8;
        float dl = sd[rl * 4] + sd[rl * 4 + 1] + sd[rl * 4 + 2] + sd[rl * 4 + 3];
        float dh = sd[rh * 4] + sd[rh * 4 + 1] + sd[rh * 4 + 2] + sd[rh * 4 + 3];
        float cl = 0.1f / dl;
        float ch = 0.1f / dh;
        const float2* x_lo = reinterpret_cast<const float2*>(x + (size_t)(r0 + rl) * DIM);
        const float2* x_hi = reinterpret_cast<const float2*>(x + (size_t)(r0 + rh) * DIM);
        float2* o_lo = reinterpret_cast<float2*>(out + (size_t)(r0 + rl) * DIM);
        float2* o_hi = reinterpret_cast<float2*>(out + (size_t)(r0 + rh) * DIM);
        #pragma unroll
        for (int q = 0; q < 4; q++) {
            #pragma unroll
            for (int jj = 0; jj < 2; jj++) {
                int cidx = (d0 + q * 16 + jj * 8 + q4 * 2) >> 1;
                int t = ma * 8 + q * 2 + jj;
                float2 olo = __half22float2(*reinterpret_cast<__half2*>(&oacc[t][0]));
                float2 ohi = __half22float2(*reinterpret_cast<__half2*>(&oacc[t][1]));
                float2 xv = x_lo[cidx];
                float2 ov;
                ov.x = 1.1f * xv.x - cl * olo.x;
                ov.y = 1.1f * xv.y - cl * olo.y;
                o_lo[cidx] = ov;
                float2 xw = x_hi[cidx];
                float2 ow;
                ow.x = 1.1f * xw.x - ch * ohi.x;
                ow.y = 1.1f * xw.y - ch * ohi.y;
                o_hi[cidx] = ow;
            }
        }
    }
}

// ---------------------------------------------------------------------------
extern "C" void kernel_launch(void* const* d_in, const int* in_sizes, int n_in,
                              void* d_out, int out_size) {
    const float* x = (const float*)d_in[0];
    float* out = (float*)d_out;

    normalize_kernel<<<N_ROWS / 8, 256>>>(x);

    cudaFuncSetAttribute(contranorm_main,
                         cudaFuncAttributeMaxDynamicSharedMemorySize, SMEM_TOTAL);
    contranorm_main<<<N_ROWS / BM, 512, SMEM_TOTAL>>>(x, out);
}

// round 16
// speedup vs baseline: 1.1035x; 1.1035x over previous
#include <cuda_runtime.h>
#include <cuda_fp16.h>
#include <cstdint>

// ============================================================================
// ContraNorm: out = 1.1*x - 0.1 * softmax(xn @ xn^T) @ x,   N=16384, D=256
// R16: split-K persistent distribution. Item space = 128 row-blocks x 128
// key-tiles; grid = #SMs (129..160), each CTA gets a contiguous item range
// (<=2 row-block segments). Loop body identical to R13 (621us). Segments
// write partial O/denom (fp32) to scratch; combine kernel sums <=3
// contributors per row block and applies the final blend.
// ============================================================================

#define N_ROWS 16384
#define DIM    256
#define BM     128
#define BN     128
#define NTILES (N_ROWS / BN)
#define NITEMS (128 * 128)
#define MAXCTA 160

__device__ __align__(16) __half g_xn[(size_t)N_ROWS * DIM];  // normalized rows (fp16)
__device__ __align__(16) __half g_xq[(size_t)N_ROWS * DIM];  // normalized * log2e
__device__ __align__(16) __half g_norm[N_ROWS];              // row L2 norms (fp16)
__device__ __align__(16) float  g_partO[MAXCTA][2][BM][DIM]; // partial O per CTA segment
__device__ __align__(16) float  g_partD[MAXCTA][2][BM];      // partial denom

// ---------------------------------------------------------------------------
__device__ __forceinline__ uint32_t smem_to_u32(const void* p) {
    uint32_t a;
    asm("{ .reg .u64 t; cvta.to.shared.u64 t, %1; cvt.u32.u64 %0, t; }" : "=r"(a) : "l"(p));
    return a;
}

__device__ __forceinline__ void ldsm_x4(uint32_t (&r)[4], uint32_t addr) {
    asm volatile("ldmatrix.sync.aligned.m8n8.x4.shared.b16 {%0,%1,%2,%3}, [%4];"
        : "=r"(r[0]), "=r"(r[1]), "=r"(r[2]), "=r"(r[3]) : "r"(addr));
}
__device__ __forceinline__ void ldsm_x4_t(uint32_t (&r)[4], uint32_t addr) {
    asm volatile("ldmatrix.sync.aligned.m8n8.x4.trans.shared.b16 {%0,%1,%2,%3}, [%4];"
        : "=r"(r[0]), "=r"(r[1]), "=r"(r[2]), "=r"(r[3]) : "r"(addr));
}

// fp32-accum fp16 mma (PV)
__device__ __forceinline__ void mma_f16(float (&c)[4], const uint32_t (&a)[4],
                                        uint32_t b0, uint32_t b1) {
    asm volatile(
        "mma.sync.aligned.m16n8k16.row.col.f32.f16.f16.f32 "
        "{%0,%1,%2,%3}, {%4,%5,%6,%7}, {%8,%9}, {%0,%1,%2,%3};"
        : "+f"(c[0]), "+f"(c[1]), "+f"(c[2]), "+f"(c[3])
        : "r"(a[0]), "r"(a[1]), "r"(a[2]), "r"(a[3]), "r"(b0), "r"(b1));
}

// fp16-accum fp16 mma (QK)
__device__ __forceinline__ void mma_f16h(uint32_t (&c)[2], const uint32_t (&a)[4],
                                         uint32_t b0, uint32_t b1) {
    asm volatile(
        "mma.sync.aligned.m16n8k16.row.col.f16.f16.f16.f16 "
        "{%0,%1}, {%2,%3,%4,%5}, {%6,%7}, {%0,%1};"
        : "+r"(c[0]), "+r"(c[1])
        : "r"(a[0]), "r"(a[1]), "r"(a[2]), "r"(a[3]), "r"(b0), "r"(b1));
}

// half2 2^x
__device__ __forceinline__ uint32_t ex2_h2(uint32_t x) {
    uint32_t y;
    asm("ex2.approx.f16x2 %0, %1;" : "=r"(y) : "r"(x));
    return y;
}

#define STS32(smem_addr, v) \
    asm volatile("st.shared.b32 [%0], %1;" :: "r"(smem_addr), "r"(v) : "memory")

#define BAR_SYNC(id, cnt) \
    asm volatile("bar.sync %0, %1;" :: "r"(id), "r"(cnt) : "memory")

#define CP_ASYNC16(dst, src) \
    asm volatile("cp.async.cg.shared.global [%0], [%1], 16;" :: "r"(dst), "l"(src) : "memory")

#define CP_MBAR_ARRIVE_NOINC(mbar) \
    asm volatile("cp.async.mbarrier.arrive.noinc.shared.b64 [%0];" :: "r"((uint32_t)(mbar)) : "memory")

#define MBARRIER_INIT(mbar, cnt) \
    asm volatile("mbarrier.init.shared.b64 [%0], %1;" :: "r"((uint32_t)(mbar)), "r"((uint32_t)(cnt)) : "memory")
#define MBARRIER_ARRIVE(mbar) \
    asm volatile("mbarrier.arrive.shared.b64 _, [%0];" :: "r"((uint32_t)(mbar)) : "memory")

#define MBARRIER_WAIT_PARITY(mbar_smem_addr, phase_parity) do { \
    uint32_t _mbar = (uint32_t)(mbar_smem_addr); \
    uint32_t _parity = (uint32_t)(phase_parity); \
    uint32_t _done; \
    asm volatile( \
        "{\n\t.reg .pred p;\n\t" \
        "mbarrier.try_wait.parity.acquire.cta.shared::cta.b64 p, [%1], %2;\n\t" \
        "selp.b32 %0, 1, 0, p;\n\t}" \
        : "=r"(_done) : "r"(_mbar), "r"(_parity) : "memory"); \
    if (!_done) { \
        asm volatile( \
            "{\n\t.reg .pred P1;\n\t" \
            "WAIT_LOOP_%=:\n\t" \
            "mbarrier.try_wait.parity.acquire.cta.shared::cta.b64 P1, [%0], %1, 0x989680;\n\t" \
            "@P1 bra.uni WAIT_DONE_%=;\n\t" \
            "bra.uni WAIT_LOOP_%=;\n\t" \
            "WAIT_DONE_%=:\n\t}" \
            :: "r"(_mbar), "r"(_parity) : "memory"); \
    } \
} while(0)

// SMEM layout (bytes)
#define SQ  0           // Q tile   [128][256] fp16, row stride 512 B (swizzled)
#define SK0 65536       // K tile buf0
#define SK1 131072      // K tile buf1
#define SP  196608      // P tile [128][128] fp16, row stride 256 B (swizzled)
#define SN  229376      // fp16 norms: 2 x 256 B
#define SMB 230400      // mbarriers: full0, full1, free0, free1 (8 B each)
#define SMEM_TOTAL 230528

// ---------------------------------------------------------------------------
// Prologue: per-row L2 normalize fp32 -> fp16 (xn and xn*log2e), fp16 norms
// ---------------------------------------------------------------------------
__global__ void normalize_kernel(const float* __restrict__ x) {
    int row  = blockIdx.x * 8 + (threadIdx.x >> 5);
    int lane = threadIdx.x & 31;
    const float4* xr = reinterpret_cast<const float4*>(x + (size_t)row * DIM);
    float4 a = xr[lane * 2];
    float4 b = xr[lane * 2 + 1];
    float ss = a.x*a.x + a.y*a.y + a.z*a.z + a.w*a.w
             + b.x*b.x + b.y*b.y + b.z*b.z + b.w*b.w;
    #pragma unroll
    for (int o = 16; o > 0; o >>= 1) ss += __shfl_xor_sync(0xFFFFFFFFu, ss, o);
    float nrm = sqrtf(ss);
    float inv = 1.0f / fmaxf(nrm, 1e-12f);
    float invq = inv * 1.4426950408889634f;   // log2(e)

    __half2 p0 = __floats2half2_rn(a.x * inv, a.y * inv);
    __half2 p1 = __floats2half2_rn(a.z * inv, a.w * inv);
    __half2 p2 = __floats2half2_rn(b.x * inv, b.y * inv);
    __half2 p3 = __floats2half2_rn(b.z * inv, b.w * inv);
    uint4 v;
    v.x = *reinterpret_cast<uint32_t*>(&p0);
    v.y = *reinterpret_cast<uint32_t*>(&p1);
    v.z = *reinterpret_cast<uint32_t*>(&p2);
    v.w = *reinterpret_cast<uint32_t*>(&p3);
    *reinterpret_cast<uint4*>(&g_xn[(size_t)row * DIM + lane * 8]) = v;

    __half2 q0 = __floats2half2_rn(a.x * invq, a.y * invq);
    __half2 q1 = __floats2half2_rn(a.z * invq, a.w * invq);
    __half2 q2 = __floats2half2_rn(b.x * invq, b.y * invq);
    __half2 q3 = __floats2half2_rn(b.z * invq, b.w * invq);
    uint4 w;
    w.x = *reinterpret_cast<uint32_t*>(&q0);
    w.y = *reinterpret_cast<uint32_t*>(&q1);
    w.z = *reinterpret_cast<uint32_t*>(&q2);
    w.w = *reinterpret_cast<uint32_t*>(&q3);
    *reinterpret_cast<uint4*>(&g_xq[(size_t)row * DIM + lane * 8]) = w;

    if (lane == 0) g_norm[row] = __float2half(nrm);
}

// ---------------------------------------------------------------------------
// async loads: Q tile for a row block; K tile (+norms) for key tile J into buf
// ---------------------------------------------------------------------------
__device__ __forceinline__ void load_q(uint32_t sb, int tid, int blk) {
    const __half* src = g_xq + (size_t)blk * BM * DIM;
    #pragma unroll
    for (int it = 0; it < 8; it++) {
        int idx = tid + it * 512;
        int row = idx >> 5;
        int c16 = idx & 31;
        uint32_t dst = sb + SQ + (uint32_t)row * 512 + (((uint32_t)c16 * 16) ^ ((row & 7) << 4));
        CP_ASYNC16(dst, src + row * DIM + c16 * 8);
    }
}

__device__ __forceinline__ void prefetch_tile(uint32_t sb, int tid, int J, int buf) {
    uint32_t kb = sb + SK0 + ((uint32_t)buf << 16);
    const __half* src = g_xn + (size_t)J * BN * DIM;
    #pragma unroll
    for (int it = 0; it < 8; it++) {
        int idx = tid + it * 512;
        int row = idx >> 5;
        int c16 = idx & 31;
        uint32_t dst = kb + (uint32_t)row * 512 + (((uint32_t)c16 * 16) ^ ((row & 7) << 4));
        CP_ASYNC16(dst, src + row * DIM + c16 * 8);
    }
    if (tid < 16) {
        uint32_t dst = sb + SN + ((uint32_t)buf << 8) + (uint32_t)tid * 16;
        CP_ASYNC16(dst, g_norm + J * BN + tid * 8);
    }
}

// ---------------------------------------------------------------------------
// Main flash kernel: grid = nCTA (one per SM), 512 threads (16 warps, 4x4)
// ---------------------------------------------------------------------------
__global__ void __launch_bounds__(512, 1)
contranorm_main(int nCTA) {
    extern __shared__ __align__(1024) char smem[];
    const uint32_t sb = smem_to_u32(smem);
    const int tid  = threadIdx.x;
    const int lane = tid & 31;
    const int wid  = tid >> 5;
    const int mi   = wid >> 2;            // 0..3 row-warp group (contiguous tids)
    const int ni   = wid & 3;             // 0..3 col-warp
    const int m0   = mi * 32;
    const int n0   = ni * 32;
    const int d0   = ni * 64;

    const int c  = blockIdx.x;
    const int t0 = (c * NITEMS) / nCTA;
    const int t1 = ((c + 1) * NITEMS) / nCTA;
    const int L  = t1 - t0;

    const uint32_t mb_full = sb + SMB;        // +0: buf0, +8: buf1
    const uint32_t mb_free = sb + SMB + 16;   // +0: buf0, +8: buf1

    const int sub = lane >> 3;
    const int li  = lane & 7;
    const uint32_t XR  = (uint32_t)li << 4;
    const uint32_t csA = (uint32_t)((sub >> 1) << 4);
    const uint32_t csB = (uint32_t)((sub & 1) << 4);
    const int rowA = li + ((sub & 1) << 3);
    const int rowB = li + ((sub >> 1) << 3);
    const uint32_t d02 = (uint32_t)d0 * 2;

    const uint32_t a_qk = sb + SQ + (uint32_t)(m0 + rowA) * 512;
    const uint32_t a_pv = sb + SP + (uint32_t)(m0 + rowA) * 256;

    const int g4 = lane >> 2;
    const int q4 = lane & 3;
    const uint32_t XRp  = (uint32_t)g4 << 4;
    const uint32_t p_st0 = sb + SP + (uint32_t)(m0 + g4) * 256;

    if (tid == 0) {
        MBARRIER_INIT(mb_full,     512);
        MBARRIER_INIT(mb_full + 8, 512);
        MBARRIER_INIT(mb_free,     16);
        MBARRIER_INIT(mb_free + 8, 16);
    }
    __syncthreads();

    // ---- initial: Q for first block + K tile for first item ----
    load_q(sb, tid, t0 >> 7);
    prefetch_tile(sb, tid, t0 & 127, 0);
    CP_MBAR_ARRIVE_NOINC(mb_full);

    float oacc[16][4];
    #pragma unroll
    for (int t = 0; t < 16; t++)
        #pragma unroll
        for (int u = 0; u < 4; u++) oacc[t][u] = 0.0f;
    float dsum[2][2] = {{0.0f, 0.0f}, {0.0f, 0.0f}};
    int seg = 0;

    for (int l = 0; l < L; l++) {
        const int t = t0 + l;
        const int J = t & 127;
        const int b = l & 1;
        const uint32_t kb = sb + SK0 + ((uint32_t)b << 16);

        MBARRIER_WAIT_PARITY(mb_full + b * 8, (l >> 1) & 1);

        // ---- QK^T: fp16 accumulate, operand double-buffered (R13) ----
        uint32_t sacc[8][2];
        #pragma unroll
        for (int tt = 0; tt < 8; tt++) { sacc[tt][0] = 0u; sacc[tt][1] = 0u; }

        const uint32_t b_qk = kb + (uint32_t)(n0 + rowB) * 512;
        {
            uint32_t fa[2][2][4];
            uint32_t fb[2][2][4];
            {
                uint32_t colA = csA ^ XR;
                uint32_t colB = csB ^ XR;
                ldsm_x4(fa[0][0], a_qk + colA);
                ldsm_x4(fa[0][1], a_qk + 8192 + colA);
                ldsm_x4(fb[0][0], b_qk + colB);
                ldsm_x4(fb[0][1], b_qk + 8192 + colB);
            }
            #pragma unroll
            for (int kk = 0; kk < 16; kk++) {
                const int cur = kk & 1, nxt = cur ^ 1;
                if (kk < 15) {
                    uint32_t colA = (((uint32_t)(kk + 1) << 5) | csA) ^ XR;
                    uint32_t colB = (((uint32_t)(kk + 1) << 5) | csB) ^ XR;
                    ldsm_x4(fa[nxt][0], a_qk + colA);
                    ldsm_x4(fa[nxt][1], a_qk + 8192 + colA);
                    ldsm_x4(fb[nxt][0], b_qk + colB);
                    ldsm_x4(fb[nxt][1], b_qk + 8192 + colB);
                }
                #pragma unroll
                for (int nb2 = 0; nb2 < 2; nb2++) {
                    mma_f16h(sacc[nb2 * 2],     fa[cur][0], fb[cur][nb2][0], fb[cur][nb2][1]);
                    mma_f16h(sacc[nb2 * 2 + 1], fa[cur][0], fb[cur][nb2][2], fb[cur][nb2][3]);
                    mma_f16h(sacc[4 + nb2 * 2],     fa[cur][1], fb[cur][nb2][0], fb[cur][nb2][1]);
                    mma_f16h(sacc[4 + nb2 * 2 + 1], fa[cur][1], fb[cur][nb2][2], fb[cur][nb2][3]);
                }
            }
        }

        // ---- prefetch next item (K tile + norms; Q too at block boundary) ----
        if (l + 1 < L) {
            if (l > 0)
                MBARRIER_WAIT_PARITY(mb_free + ((l + 1) & 1) * 8, ((l - 1) >> 1) & 1);
            if (((t + 1) & 127) == 0) {
                // next item starts a new row block: everyone is past QK(l),
                // so Q can be overwritten (uniform branch)
                __syncthreads();
                load_q(sb, tid, (t + 1) >> 7);
            }
            prefetch_tile(sb, tid, (t + 1) & 127, (l + 1) & 1);
            CP_MBAR_ARRIVE_NOINC(mb_full + ((l + 1) & 1) * 8);
        }

        // ---- epilogue (half2): e = 2^(S'); denom += e; P = e*norm_n ----
        const __half2* nrmh = reinterpret_cast<const __half2*>(smem + SN + (b << 8));
        uint32_t pa[2][4][2];
        #pragma unroll
        for (int ma = 0; ma < 2; ma++) {
            __half2 hs0 = __float2half2_rn(0.0f);
            __half2 hs1 = __float2half2_rn(0.0f);
            #pragma unroll
            for (int nb = 0; nb < 4; nb++) {
                int cc = n0 + nb * 8 + q4 * 2;
                __half2 nn = nrmh[cc >> 1];
                uint32_t e01u = ex2_h2(sacc[ma * 4 + nb][0]);
                uint32_t e23u = ex2_h2(sacc[ma * 4 + nb][1]);
                __half2 e01 = *reinterpret_cast<__half2*>(&e01u);
                __half2 e23 = *reinterpret_cast<__half2*>(&e23u);
                hs0 = __hadd2(hs0, e01);
                hs1 = __hadd2(hs1, e23);
                __half2 p01 = __hmul2(e01, nn);
                __half2 p23 = __hmul2(e23, nn);
                uint32_t ulo = *reinterpret_cast<uint32_t*>(&p01);
                uint32_t uhi = *reinterpret_cast<uint32_t*>(&p23);
                pa[ma][nb][0] = ulo;
                pa[ma][nb][1] = uhi;
                uint32_t addr = p_st0 + (uint32_t)ma * 4096 + (((uint32_t)cc * 2) ^ XRp);
                STS32(addr, ulo);
                STS32(addr + 2048, uhi);
            }
            float2 f0 = __half22float2(hs0);
            float2 f1 = __half22float2(hs1);
            dsum[ma][0] += f0.x + f0.y;
            dsum[ma][1] += f1.x + f1.y;
        }

        // ---- PV own-key steps (A from pa registers) before the group barrier ----
        const uint32_t b_pv = kb + (uint32_t)rowA * 512;
        #pragma unroll
        for (int t2 = 0; t2 < 2; t2++) {
            int kk = 2 * ni + t2;
            uint32_t a0[4], a1[4];
            a0[0] = pa[0][t2 * 2][0];     a0[1] = pa[0][t2 * 2][1];
            a0[2] = pa[0][t2 * 2 + 1][0]; a0[3] = pa[0][t2 * 2 + 1][1];
            a1[0] = pa[1][t2 * 2][0];     a1[1] = pa[1][t2 * 2][1];
            a1[2] = pa[1][t2 * 2 + 1][0]; a1[3] = pa[1][t2 * 2 + 1][1];
            uint32_t rbase = b_pv + (uint32_t)kk * 8192;
            #pragma unroll
            for (int q = 0; q < 4; q++) {
                uint32_t b2[4];
                ldsm_x4_t(b2, rbase + ((d02 + ((uint32_t)q << 5) + csA) ^ XR));
                mma_f16(oacc[q * 2],     a0, b2[0], b2[1]);
                mma_f16(oacc[q * 2 + 1], a0, b2[2], b2[3]);
                mma_f16(oacc[8 + q * 2],     a1, b2[0], b2[1]);
                mma_f16(oacc[8 + q * 2 + 1], a1, b2[2], b2[3]);
            }
        }

        BAR_SYNC(1 + mi, 128);

        // ---- PV remaining steps: A via ldsm of P tile ----
        #pragma unroll
        for (int kk = 0; kk < 8; kk++) {
            if ((kk >> 1) == ni) continue;
            uint32_t a0[4], a1[4];
            uint32_t colA = (((uint32_t)kk << 5) | csA) ^ XR;
            ldsm_x4(a0, a_pv + colA);
            ldsm_x4(a1, a_pv + 4096 + colA);
            uint32_t rbase = b_pv + (uint32_t)kk * 8192;
            #pragma unroll
            for (int q = 0; q < 4; q++) {
                uint32_t b2[4];
                ldsm_x4_t(b2, rbase + ((d02 + ((uint32_t)q << 5) + csA) ^ XR));
                mma_f16(oacc[q * 2],     a0, b2[0], b2[1]);
                mma_f16(oacc[q * 2 + 1], a0, b2[2], b2[3]);
                mma_f16(oacc[8 + q * 2],     a1, b2[0], b2[1]);
                mma_f16(oacc[8 + q * 2 + 1], a1, b2[2], b2[3]);
            }
        }
        BAR_SYNC(1 + mi, 128);
        if (lane == 0) MBARRIER_ARRIVE(mb_free + b * 8);

        // ---- segment end: flush partial O + denom, reset accumulators ----
        if (J == 127 || l == L - 1) {
            __syncthreads();               // all PV reads of P done
            float* sd = reinterpret_cast<float*>(smem + SP);
            #pragma unroll
            for (int ma = 0; ma < 2; ma++) {
                #pragma unroll
                for (int lh = 0; lh < 2; lh++) {
                    float d = dsum[ma][lh];
                    d += __shfl_xor_sync(0xFFFFFFFFu, d, 1);
                    d += __shfl_xor_sync(0xFFFFFFFFu, d, 2);
                    if (q4 == 0) sd[(m0 + ma * 16 + lh * 8 + g4) * 4 + ni] = d;
                }
            }
            __syncthreads();
            float* po = &g_partO[c][seg][0][0];
            float* pd = &g_partD[c][seg][0];
            #pragma unroll
            for (int ma = 0; ma < 2; ma++) {
                int rl = m0 + ma * 16 + g4;
                int rh = rl + 8;
                float dl = sd[rl * 4] + sd[rl * 4 + 1] + sd[rl * 4 + 2] + sd[rl * 4 + 3];
                float dh = sd[rh * 4] + sd[rh * 4 + 1] + sd[rh * 4 + 2] + sd[rh * 4 + 3];
                if (q4 == 0) { pd[rl] = dl; pd[rh] = dh; }
                float* porl = po + (size_t)rl * DIM;
                float* porh = po + (size_t)rh * DIM;
                #pragma unroll
                for (int q = 0; q < 4; q++) {
                    #pragma unroll
                    for (int jj = 0; jj < 2; jj++) {
                        int col = d0 + q * 16 + jj * 8 + q4 * 2;
                        const float* o4 = oacc[ma * 8 + q * 2 + jj];
                        *reinterpret_cast<float2*>(porl + col) = make_float2(o4[0], o4[1]);
                        *reinterpret_cast<float2*>(porh + col) = make_float2(o4[2], o4[3]);
                    }
                }
            }
            #pragma unroll
            for (int tt = 0; tt < 16; tt++)
                #pragma unroll
                for (int u = 0; u < 4; u++) oacc[tt][u] = 0.0f;
            dsum[0][0] = dsum[0][1] = dsum[1][0] = dsum[1][1] = 0.0f;
            seg++;
            __syncthreads();               // sd reads done before P reused
        }
    }
}

// ---------------------------------------------------------------------------
// Combine: per row, sum <=3 contributing segments, apply final blend
// ---------------------------------------------------------------------------
__global__ void combine_kernel(const float* __restrict__ x, float* __restrict__ out,
                               int nCTA) {
    int r    = blockIdx.x * 8 + (threadIdx.x >> 5);
    int lane = threadIdx.x & 31;
    int I    = r >> 7;
    int rloc = r & 127;

    float d = 0.0f;
    float acc[8] = {0, 0, 0, 0, 0, 0, 0, 0};

    int c0 = ((128 * I + 1) * nCTA - 1) / NITEMS;   // CTA containing item 128*I
    if (c0 > 0) c0--;                                // safety margin
    #pragma unroll 1
    for (int cc = c0; cc < c0 + 5 && cc < nCTA; cc++) {
        int s0 = (cc * NITEMS) / nCTA;
        int s1 = ((cc + 1) * NITEMS) / nCTA;
        if (s0 >= (I + 1) * 128) break;
        if (s1 <= I * 128) continue;
        int seg = I - (s0 >> 7);
        if (seg < 0 || seg > 1) continue;
        d += g_partD[cc][seg][rloc];
        const float4* po = reinterpret_cast<const float4*>(&g_partO[cc][seg][rloc][lane * 8]);
        float4 a = po[0], b = po[1];
        acc[0] += a.x; acc[1] += a.y; acc[2] += a.z; acc[3] += a.w;
        acc[4] += b.x; acc[5] += b.y; acc[6] += b.z; acc[7] += b.w;
    }

    float coef = 0.1f / d;
    const float4* xr = reinterpret_cast<const float4*>(x + (size_t)r * DIM + lane * 8);
    float4 xa = xr[0], xb = xr[1];
    float4 oa, ob;
    oa.x = 1.1f * xa.x - coef * acc[0];
    oa.y = 1.1f * xa.y - coef * acc[1];
    oa.z = 1.1f * xa.z - coef * acc[2];
    oa.w = 1.1f * xa.w - coef * acc[3];
    ob.x = 1.1f * xb.x - coef * acc[4];
    ob.y = 1.1f * xb.y - coef * acc[5];
    ob.z = 1.1f * xb.z - coef * acc[6];
    ob.w = 1.1f * xb.w - coef * acc[7];
    float4* orow = reinterpret_cast<float4*>(out + (size_t)r * DIM + lane * 8);
    orow[0] = oa;
    orow[1] = ob;
}

// ---------------------------------------------------------------------------
extern "C" void kernel_launch(void* const* d_in, const int* in_sizes, int n_in,
                              void* d_out, int out_size) {
    const float* x = (const float*)d_in[0];
    float* out = (float*)d_out;

    int sm = 0;
    cudaDeviceGetAttribute(&sm, cudaDevAttrMultiProcessorCount, 0);
    int nCTA = sm;
    if (nCTA < 129) nCTA = 148;     // guarantee each range <= 127 items
    if (nCTA > MAXCTA) nCTA = MAXCTA;

    normalize_kernel<<<N_ROWS / 8, 256>>>(x);

    cudaFuncSetAttribute(contranorm_main,
                         cudaFuncAttributeMaxDynamicSharedMemorySize, SMEM_TOTAL);
    contranorm_main<<<nCTA, 512, SMEM_TOTAL>>>(nCTA);

    combine_kernel<<<N_ROWS / 8, 256>>>(x, out, nCTA);
}

// round 17
// speedup vs baseline: 1.1557x; 1.0473x over previous
#include <cuda_runtime.h>
#include <cuda_fp16.h>
#include <cstdint>

// ============================================================================
// ContraNorm: out = 1.1*x - 0.1 * softmax(xn @ xn^T) @ x,   N=16384, D=256
// R17: split-K persistent distribution (R16) + fp16 O accumulators (R13) to
// eliminate register spills (fp32 oacc + dual operand buffers exceeded the
// 128-reg cap). Partials still flushed in fp32; combine kernel unchanged.
// ============================================================================

#define N_ROWS 16384
#define DIM    256
#define BM     128
#define BN     128
#define NTILES (N_ROWS / BN)
#define NITEMS (128 * 128)
#define MAXCTA 160

__device__ __align__(16) __half g_xn[(size_t)N_ROWS * DIM];  // normalized rows (fp16)
__device__ __align__(16) __half g_xq[(size_t)N_ROWS * DIM];  // normalized * log2e
__device__ __align__(16) __half g_norm[N_ROWS];              // row L2 norms (fp16)
__device__ __align__(16) float  g_partO[MAXCTA][2][BM][DIM]; // partial O per CTA segment
__device__ __align__(16) float  g_partD[MAXCTA][2][BM];      // partial denom

// ---------------------------------------------------------------------------
__device__ __forceinline__ uint32_t smem_to_u32(const void* p) {
    uint32_t a;
    asm("{ .reg .u64 t; cvta.to.shared.u64 t, %1; cvt.u32.u64 %0, t; }" : "=r"(a) : "l"(p));
    return a;
}

__device__ __forceinline__ void ldsm_x4(uint32_t (&r)[4], uint32_t addr) {
    asm volatile("ldmatrix.sync.aligned.m8n8.x4.shared.b16 {%0,%1,%2,%3}, [%4];"
        : "=r"(r[0]), "=r"(r[1]), "=r"(r[2]), "=r"(r[3]) : "r"(addr));
}
__device__ __forceinline__ void ldsm_x4_t(uint32_t (&r)[4], uint32_t addr) {
    asm volatile("ldmatrix.sync.aligned.m8n8.x4.trans.shared.b16 {%0,%1,%2,%3}, [%4];"
        : "=r"(r[0]), "=r"(r[1]), "=r"(r[2]), "=r"(r[3]) : "r"(addr));
}

// fp16-accum fp16 mma (QK and PV)
__device__ __forceinline__ void mma_f16h(uint32_t (&c)[2], const uint32_t (&a)[4],
                                         uint32_t b0, uint32_t b1) {
    asm volatile(
        "mma.sync.aligned.m16n8k16.row.col.f16.f16.f16.f16 "
        "{%0,%1}, {%2,%3,%4,%5}, {%6,%7}, {%0,%1};"
        : "+r"(c[0]), "+r"(c[1])
        : "r"(a[0]), "r"(a[1]), "r"(a[2]), "r"(a[3]), "r"(b0), "r"(b1));
}

// half2 2^x
__device__ __forceinline__ uint32_t ex2_h2(uint32_t x) {
    uint32_t y;
    asm("ex2.approx.f16x2 %0, %1;" : "=r"(y) : "r"(x));
    return y;
}

#define STS32(smem_addr, v) \
    asm volatile("st.shared.b32 [%0], %1;" :: "r"(smem_addr), "r"(v) : "memory")

#define BAR_SYNC(id, cnt) \
    asm volatile("bar.sync %0, %1;" :: "r"(id), "r"(cnt) : "memory")

#define CP_ASYNC16(dst, src) \
    asm volatile("cp.async.cg.shared.global [%0], [%1], 16;" :: "r"(dst), "l"(src) : "memory")

#define CP_MBAR_ARRIVE_NOINC(mbar) \
    asm volatile("cp.async.mbarrier.arrive.noinc.shared.b64 [%0];" :: "r"((uint32_t)(mbar)) : "memory")

#define MBARRIER_INIT(mbar, cnt) \
    asm volatile("mbarrier.init.shared.b64 [%0], %1;" :: "r"((uint32_t)(mbar)), "r"((uint32_t)(cnt)) : "memory")
#define MBARRIER_ARRIVE(mbar) \
    asm volatile("mbarrier.arrive.shared.b64 _, [%0];" :: "r"((uint32_t)(mbar)) : "memory")

#define MBARRIER_WAIT_PARITY(mbar_smem_addr, phase_parity) do { \
    uint32_t _mbar = (uint32_t)(mbar_smem_addr); \
    uint32_t _parity = (uint32_t)(phase_parity); \
    uint32_t _done; \
    asm volatile( \
        "{\n\t.reg .pred p;\n\t" \
        "mbarrier.try_wait.parity.acquire.cta.shared::cta.b64 p, [%1], %2;\n\t" \
        "selp.b32 %0, 1, 0, p;\n\t}" \
        : "=r"(_done) : "r"(_mbar), "r"(_parity) : "memory"); \
    if (!_done) { \
        asm volatile( \
            "{\n\t.reg .pred P1;\n\t" \
            "WAIT_LOOP_%=:\n\t" \
            "mbarrier.try_wait.parity.acquire.cta.shared::cta.b64 P1, [%0], %1, 0x989680;\n\t" \
            "@P1 bra.uni WAIT_DONE_%=;\n\t" \
            "bra.uni WAIT_LOOP_%=;\n\t" \
            "WAIT_DONE_%=:\n\t}" \
            :: "r"(_mbar), "r"(_parity) : "memory"); \
    } \
} while(0)

// SMEM layout (bytes)
#define SQ  0           // Q tile   [128][256] fp16, row stride 512 B (swizzled)
#define SK0 65536       // K tile buf0
#define SK1 131072      // K tile buf1
#define SP  196608      // P tile [128][128] fp16, row stride 256 B (swizzled)
#define SN  229376      // fp16 norms: 2 x 256 B
#define SMB 230400      // mbarriers: full0, full1, free0, free1 (8 B each)
#define SMEM_TOTAL 230528

// ---------------------------------------------------------------------------
// Prologue: per-row L2 normalize fp32 -> fp16 (xn and xn*log2e), fp16 norms
// ---------------------------------------------------------------------------
__global__ void normalize_kernel(const float* __restrict__ x) {
    int row  = blockIdx.x * 8 + (threadIdx.x >> 5);
    int lane = threadIdx.x & 31;
    const float4* xr = reinterpret_cast<const float4*>(x + (size_t)row * DIM);
    float4 a = xr[lane * 2];
    float4 b = xr[lane * 2 + 1];
    float ss = a.x*a.x + a.y*a.y + a.z*a.z + a.w*a.w
             + b.x*b.x + b.y*b.y + b.z*b.z + b.w*b.w;
    #pragma unroll
    for (int o = 16; o > 0; o >>= 1) ss += __shfl_xor_sync(0xFFFFFFFFu, ss, o);
    float nrm = sqrtf(ss);
    float inv = 1.0f / fmaxf(nrm, 1e-12f);
    float invq = inv * 1.4426950408889634f;   // log2(e)

    __half2 p0 = __floats2half2_rn(a.x * inv, a.y * inv);
    __half2 p1 = __floats2half2_rn(a.z * inv, a.w * inv);
    __half2 p2 = __floats2half2_rn(b.x * inv, b.y * inv);
    __half2 p3 = __floats2half2_rn(b.z * inv, b.w * inv);
    uint4 v;
    v.x = *reinterpret_cast<uint32_t*>(&p0);
    v.y = *reinterpret_cast<uint32_t*>(&p1);
    v.z = *reinterpret_cast<uint32_t*>(&p2);
    v.w = *reinterpret_cast<uint32_t*>(&p3);
    *reinterpret_cast<uint4*>(&g_xn[(size_t)row * DIM + lane * 8]) = v;

    __half2 q0 = __floats2half2_rn(a.x * invq, a.y * invq);
    __half2 q1 = __floats2half2_rn(a.z * invq, a.w * invq);
    __half2 q2 = __floats2half2_rn(b.x * invq, b.y * invq);
    __half2 q3 = __floats2half2_rn(b.z * invq, b.w * invq);
    uint4 w;
    w.x = *reinterpret_cast<uint32_t*>(&q0);
    w.y = *reinterpret_cast<uint32_t*>(&q1);
    w.z = *reinterpret_cast<uint32_t*>(&q2);
    w.w = *reinterpret_cast<uint32_t*>(&q3);
    *reinterpret_cast<uint4*>(&g_xq[(size_t)row * DIM + lane * 8]) = w;

    if (lane == 0) g_norm[row] = __float2half(nrm);
}

// ---------------------------------------------------------------------------
// async loads: Q tile for a row block; K tile (+norms) for key tile J into buf
// ---------------------------------------------------------------------------
__device__ __forceinline__ void load_q(uint32_t sb, int tid, int blk) {
    const __half* src = g_xq + (size_t)blk * BM * DIM;
    #pragma unroll
    for (int it = 0; it < 8; it++) {
        int idx = tid + it * 512;
        int row = idx >> 5;
        int c16 = idx & 31;
        uint32_t dst = sb + SQ + (uint32_t)row * 512 + (((uint32_t)c16 * 16) ^ ((row & 7) << 4));
        CP_ASYNC16(dst, src + row * DIM + c16 * 8);
    }
}

__device__ __forceinline__ void prefetch_tile(uint32_t sb, int tid, int J, int buf) {
    uint32_t kb = sb + SK0 + ((uint32_t)buf << 16);
    const __half* src = g_xn + (size_t)J * BN * DIM;
    #pragma unroll
    for (int it = 0; it < 8; it++) {
        int idx = tid + it * 512;
        int row = idx >> 5;
        int c16 = idx & 31;
        uint32_t dst = kb + (uint32_t)row * 512 + (((uint32_t)c16 * 16) ^ ((row & 7) << 4));
        CP_ASYNC16(dst, src + row * DIM + c16 * 8);
    }
    if (tid < 16) {
        uint32_t dst = sb + SN + ((uint32_t)buf << 8) + (uint32_t)tid * 16;
        CP_ASYNC16(dst, g_norm + J * BN + tid * 8);
    }
}

// ---------------------------------------------------------------------------
// Main flash kernel: grid = nCTA (one per SM), 512 threads (16 warps, 4x4)
// ---------------------------------------------------------------------------
__global__ void __launch_bounds__(512, 1)
contranorm_main(int nCTA) {
    extern __shared__ __align__(1024) char smem[];
    const uint32_t sb = smem_to_u32(smem);
    const int tid  = threadIdx.x;
    const int lane = tid & 31;
    const int wid  = tid >> 5;
    const int mi   = wid >> 2;            // 0..3 row-warp group (contiguous tids)
    const int ni   = wid & 3;             // 0..3 col-warp
    const int m0   = mi * 32;
    const int n0   = ni * 32;
    const int d0   = ni * 64;

    const int c  = blockIdx.x;
    const int t0 = (c * NITEMS) / nCTA;
    const int t1 = ((c + 1) * NITEMS) / nCTA;
    const int L  = t1 - t0;

    const uint32_t mb_full = sb + SMB;        // +0: buf0, +8: buf1
    const uint32_t mb_free = sb + SMB + 16;   // +0: buf0, +8: buf1

    const int sub = lane >> 3;
    const int li  = lane & 7;
    const uint32_t XR  = (uint32_t)li << 4;
    const uint32_t csA = (uint32_t)((sub >> 1) << 4);
    const uint32_t csB = (uint32_t)((sub & 1) << 4);
    const int rowA = li + ((sub & 1) << 3);
    const int rowB = li + ((sub >> 1) << 3);
    const uint32_t d02 = (uint32_t)d0 * 2;

    const uint32_t a_qk = sb + SQ + (uint32_t)(m0 + rowA) * 512;
    const uint32_t a_pv = sb + SP + (uint32_t)(m0 + rowA) * 256;

    const int g4 = lane >> 2;
    const int q4 = lane & 3;
    const uint32_t XRp  = (uint32_t)g4 << 4;
    const uint32_t p_st0 = sb + SP + (uint32_t)(m0 + g4) * 256;

    if (tid == 0) {
        MBARRIER_INIT(mb_full,     512);
        MBARRIER_INIT(mb_full + 8, 512);
        MBARRIER_INIT(mb_free,     16);
        MBARRIER_INIT(mb_free + 8, 16);
    }
    __syncthreads();

    // ---- initial: Q for first block + K tile for first item ----
    load_q(sb, tid, t0 >> 7);
    prefetch_tile(sb, tid, t0 & 127, 0);
    CP_MBAR_ARRIVE_NOINC(mb_full);

    uint32_t oacc[16][2];                  // fp16x2 O accumulators
    #pragma unroll
    for (int t = 0; t < 16; t++) { oacc[t][0] = 0u; oacc[t][1] = 0u; }
    float dsum[2][2] = {{0.0f, 0.0f}, {0.0f, 0.0f}};
    int seg = 0;

    for (int l = 0; l < L; l++) {
        const int t = t0 + l;
        const int J = t & 127;
        const int b = l & 1;
        const uint32_t kb = sb + SK0 + ((uint32_t)b << 16);

        MBARRIER_WAIT_PARITY(mb_full + b * 8, (l >> 1) & 1);

        // ---- QK^T: fp16 accumulate, operand double-buffered (R13) ----
        uint32_t sacc[8][2];
        #pragma unroll
        for (int tt = 0; tt < 8; tt++) { sacc[tt][0] = 0u; sacc[tt][1] = 0u; }

        const uint32_t b_qk = kb + (uint32_t)(n0 + rowB) * 512;
        {
            uint32_t fa[2][2][4];
            uint32_t fb[2][2][4];
            {
                uint32_t colA = csA ^ XR;
                uint32_t colB = csB ^ XR;
                ldsm_x4(fa[0][0], a_qk + colA);
                ldsm_x4(fa[0][1], a_qk + 8192 + colA);
                ldsm_x4(fb[0][0], b_qk + colB);
                ldsm_x4(fb[0][1], b_qk + 8192 + colB);
            }
            #pragma unroll
            for (int kk = 0; kk < 16; kk++) {
                const int cur = kk & 1, nxt = cur ^ 1;
                if (kk < 15) {
                    uint32_t colA = (((uint32_t)(kk + 1) << 5) | csA) ^ XR;
                    uint32_t colB = (((uint32_t)(kk + 1) << 5) | csB) ^ XR;
                    ldsm_x4(fa[nxt][0], a_qk + colA);
                    ldsm_x4(fa[nxt][1], a_qk + 8192 + colA);
                    ldsm_x4(fb[nxt][0], b_qk + colB);
                    ldsm_x4(fb[nxt][1], b_qk + 8192 + colB);
                }
                #pragma unroll
                for (int nb2 = 0; nb2 < 2; nb2++) {
                    mma_f16h(sacc[nb2 * 2],     fa[cur][0], fb[cur][nb2][0], fb[cur][nb2][1]);
                    mma_f16h(sacc[nb2 * 2 + 1], fa[cur][0], fb[cur][nb2][2], fb[cur][nb2][3]);
                    mma_f16h(sacc[4 + nb2 * 2],     fa[cur][1], fb[cur][nb2][0], fb[cur][nb2][1]);
                    mma_f16h(sacc[4 + nb2 * 2 + 1], fa[cur][1], fb[cur][nb2][2], fb[cur][nb2][3]);
                }
            }
        }

        // ---- prefetch next item (K tile + norms; Q too at block boundary) ----
        if (l + 1 < L) {
            if (l > 0)
                MBARRIER_WAIT_PARITY(mb_free + ((l + 1) & 1) * 8, ((l - 1) >> 1) & 1);
            if (((t + 1) & 127) == 0) {
                // next item starts a new row block: everyone is past QK(l),
                // so Q can be overwritten (uniform branch)
                __syncthreads();
                load_q(sb, tid, (t + 1) >> 7);
            }
            prefetch_tile(sb, tid, (t + 1) & 127, (l + 1) & 1);
            CP_MBAR_ARRIVE_NOINC(mb_full + ((l + 1) & 1) * 8);
        }

        // ---- epilogue (half2): e = 2^(S'); denom += e; P = e*norm_n ----
        const __half2* nrmh = reinterpret_cast<const __half2*>(smem + SN + (b << 8));
        uint32_t pa[2][4][2];
        #pragma unroll
        for (int ma = 0; ma < 2; ma++) {
            __half2 hs0 = __float2half2_rn(0.0f);
            __half2 hs1 = __float2half2_rn(0.0f);
            #pragma unroll
            for (int nb = 0; nb < 4; nb++) {
                int cc = n0 + nb * 8 + q4 * 2;
                __half2 nn = nrmh[cc >> 1];
                uint32_t e01u = ex2_h2(sacc[ma * 4 + nb][0]);
                uint32_t e23u = ex2_h2(sacc[ma * 4 + nb][1]);
                __half2 e01 = *reinterpret_cast<__half2*>(&e01u);
                __half2 e23 = *reinterpret_cast<__half2*>(&e23u);
                hs0 = __hadd2(hs0, e01);
                hs1 = __hadd2(hs1, e23);
                __half2 p01 = __hmul2(e01, nn);
                __half2 p23 = __hmul2(e23, nn);
                uint32_t ulo = *reinterpret_cast<uint32_t*>(&p01);
                uint32_t uhi = *reinterpret_cast<uint32_t*>(&p23);
                pa[ma][nb][0] = ulo;
                pa[ma][nb][1] = uhi;
                uint32_t addr = p_st0 + (uint32_t)ma * 4096 + (((uint32_t)cc * 2) ^ XRp);
                STS32(addr, ulo);
                STS32(addr + 2048, uhi);
            }
            float2 f0 = __half22float2(hs0);
            float2 f1 = __half22float2(hs1);
            dsum[ma][0] += f0.x + f0.y;
            dsum[ma][1] += f1.x + f1.y;
        }

        // ---- PV own-key steps (A from pa registers) before the group barrier ----
        const uint32_t b_pv = kb + (uint32_t)rowA * 512;
        #pragma unroll
        for (int t2 = 0; t2 < 2; t2++) {
            int kk = 2 * ni + t2;
            uint32_t a0[4], a1[4];
            a0[0] = pa[0][t2 * 2][0];     a0[1] = pa[0][t2 * 2][1];
            a0[2] = pa[0][t2 * 2 + 1][0]; a0[3] = pa[0][t2 * 2 + 1][1];
            a1[0] = pa[1][t2 * 2][0];     a1[1] = pa[1][t2 * 2][1];
            a1[2] = pa[1][t2 * 2 + 1][0]; a1[3] = pa[1][t2 * 2 + 1][1];
            uint32_t rbase = b_pv + (uint32_t)kk * 8192;
            #pragma unroll
            for (int q = 0; q < 4; q++) {
                uint32_t b2[4];
                ldsm_x4_t(b2, rbase + ((d02 + ((uint32_t)q << 5) + csA) ^ XR));
                mma_f16h(oacc[q * 2],     a0, b2[0], b2[1]);
                mma_f16h(oacc[q * 2 + 1], a0, b2[2], b2[3]);
                mma_f16h(oacc[8 + q * 2],     a1, b2[0], b2[1]);
                mma_f16h(oacc[8 + q * 2 + 1], a1, b2[2], b2[3]);
            }
        }

        BAR_SYNC(1 + mi, 128);

        // ---- PV remaining steps: A via ldsm of P tile ----
        #pragma unroll
        for (int kk = 0; kk < 8; kk++) {
            if ((kk >> 1) == ni) continue;
            uint32_t a0[4], a1[4];
            uint32_t colA = (((uint32_t)kk << 5) | csA) ^ XR;
            ldsm_x4(a0, a_pv + colA);
            ldsm_x4(a1, a_pv + 4096 + colA);
            uint32_t rbase = b_pv + (uint32_t)kk * 8192;
            #pragma unroll
            for (int q = 0; q < 4; q++) {
                uint32_t b2[4];
                ldsm_x4_t(b2, rbase + ((d02 + ((uint32_t)q << 5) + csA) ^ XR));
                mma_f16h(oacc[q * 2],     a0, b2[0], b2[1]);
                mma_f16h(oacc[q * 2 + 1], a0, b2[2], b2[3]);
                mma_f16h(oacc[8 + q * 2],     a1, b2[0], b2[1]);
                mma_f16h(oacc[8 + q * 2 + 1], a1, b2[2], b2[3]);
            }
        }
        BAR_SYNC(1 + mi, 128);
        if (lane == 0) MBARRIER_ARRIVE(mb_free + b * 8);

        // ---- segment end: flush partial O + denom, reset accumulators ----
        if (J == 127 || l == L - 1) {
            __syncthreads();               // all PV reads of P done
            float* sd = reinterpret_cast<float*>(smem + SP);
            #pragma unroll
            for (int ma = 0; ma < 2; ma++) {
                #pragma unroll
                for (int lh = 0; lh < 2; lh++) {
                    float d = dsum[ma][lh];
                    d += __shfl_xor_sync(0xFFFFFFFFu, d, 1);
                    d += __shfl_xor_sync(0xFFFFFFFFu, d, 2);
                    if (q4 == 0) sd[(m0 + ma * 16 + lh * 8 + g4) * 4 + ni] = d;
                }
            }
            __syncthreads();
            float* po = &g_partO[c][seg][0][0];
            float* pd = &g_partD[c][seg][0];
            #pragma unroll
            for (int ma = 0; ma < 2; ma++) {
                int rl = m0 + ma * 16 + g4;
                int rh = rl + 8;
                float dl = sd[rl * 4] + sd[rl * 4 + 1] + sd[rl * 4 + 2] + sd[rl * 4 + 3];
                float dh = sd[rh * 4] + sd[rh * 4 + 1] + sd[rh * 4 + 2] + sd[rh * 4 + 3];
                if (q4 == 0) { pd[rl] = dl; pd[rh] = dh; }
                float* porl = po + (size_t)rl * DIM;
                float* porh = po + (size_t)rh * DIM;
                #pragma unroll
                for (int q = 0; q < 4; q++) {
                    #pragma unroll
                    for (int jj = 0; jj < 2; jj++) {
                        int col = d0 + q * 16 + jj * 8 + q4 * 2;
                        int tt = ma * 8 + q * 2 + jj;
                        float2 olo = __half22float2(*reinterpret_cast<__half2*>(&oacc[tt][0]));
                        float2 ohi = __half22float2(*reinterpret_cast<__half2*>(&oacc[tt][1]));
                        *reinterpret_cast<float2*>(porl + col) = olo;
                        *reinterpret_cast<float2*>(porh + col) = ohi;
                    }
                }
            }
            #pragma unroll
            for (int tt = 0; tt < 16; tt++) { oacc[tt][0] = 0u; oacc[tt][1] = 0u; }
            dsum[0][0] = dsum[0][1] = dsum[1][0] = dsum[1][1] = 0.0f;
            seg++;
            __syncthreads();               // sd reads done before P reused
        }
    }
}

// ---------------------------------------------------------------------------
// Combine: per row, sum <=3 contributing segments, apply final blend
// ---------------------------------------------------------------------------
__global__ void combine_kernel(const float* __restrict__ x, float* __restrict__ out,
                               int nCTA) {
    int r    = blockIdx.x * 8 + (threadIdx.x >> 5);
    int lane = threadIdx.x & 31;
    int I    = r >> 7;
    int rloc = r & 127;

    float d = 0.0f;
    float acc[8] = {0, 0, 0, 0, 0, 0, 0, 0};

    int c0 = ((128 * I + 1) * nCTA - 1) / NITEMS;   // CTA containing item 128*I
    if (c0 > 0) c0--;                                // safety margin
    #pragma unroll 1
    for (int cc = c0; cc < c0 + 5 && cc < nCTA; cc++) {
        int s0 = (cc * NITEMS) / nCTA;
        int s1 = ((cc + 1) * NITEMS) / nCTA;
        if (s0 >= (I + 1) * 128) break;
        if (s1 <= I * 128) continue;
        int seg = I - (s0 >> 7);
        if (seg < 0 || seg > 1) continue;
        d += g_partD[cc][seg][rloc];
        const float4* po = reinterpret_cast<const float4*>(&g_partO[cc][seg][rloc][lane * 8]);
        float4 a = po[0], b = po[1];
        acc[0] += a.x; acc[1] += a.y; acc[2] += a.z; acc[3] += a.w;
        acc[4] += b.x; acc[5] += b.y; acc[6] += b.z; acc[7] += b.w;
    }

    float coef = 0.1f / d;
    const float4* xr = reinterpret_cast<const float4*>(x + (size_t)r * DIM + lane * 8);
    float4 xa = xr[0], xb = xr[1];
    float4 oa, ob;
    oa.x = 1.1f * xa.x - coef * acc[0];
    oa.y = 1.1f * xa.y - coef * acc[1];
    oa.z = 1.1f * xa.z - coef * acc[2];
    oa.w = 1.1f * xa.w - coef * acc[3];
    ob.x = 1.1f * xb.x - coef * acc[4];
    ob.y = 1.1f * xb.y - coef * acc[5];
    ob.z = 1.1f * xb.z - coef * acc[6];
    ob.w = 1.1f * xb.w - coef * acc[7];
    float4* orow = reinterpret_cast<float4*>(out + (size_t)r * DIM + lane * 8);
    orow[0] = oa;
    orow[1] = ob;
}

// ---------------------------------------------------------------------------
extern "C" void kernel_launch(void* const* d_in, const int* in_sizes, int n_in,
                              void* d_out, int out_size) {
    const float* x = (const float*)d_in[0];
    float* out = (float*)d_out;

    int sm = 0;
    cudaDeviceGetAttribute(&sm, cudaDevAttrMultiProcessorCount, 0);
    int nCTA = sm;
    if (nCTA < 129) nCTA = 148;     // guarantee each range <= 127 items
    if (nCTA > MAXCTA) nCTA = MAXCTA;

    normalize_kernel<<<N_ROWS / 8, 256>>>(x);

    cudaFuncSetAttribute(contranorm_main,
                         cudaFuncAttributeMaxDynamicSharedMemorySize, SMEM_TOTAL);
    contranorm_main<<<nCTA, 512, SMEM_TOTAL>>>(nCTA);

    combine_kernel<<<N_ROWS / 8, 256>>>(x, out, nCTA);
}